// round 2
// baseline (speedup 1.0000x reference)
#include <cuda_runtime.h>
#include <cstdint>
#include <cstddef>

#define Bb   8
#define Nn   256
#define Mm   512
#define EXTm 768
#define Ee   1024
#define Hh   32
#define TN   16
#define SCALING 0.17677669529663687f
#define NEGINF  -3.402823466e38f

// ---------------- scratch (static device globals; no allocs allowed) ----------------
__device__ float g_q [(size_t)Bb*Nn*Ee];
__device__ float g_k [(size_t)Bb*EXTm*Ee];
__device__ float g_v [(size_t)Bb*EXTm*Ee];
__device__ float g_ve[(size_t)Bb*EXTm*Ee];
__device__ float g_xo[(size_t)Bb*Nn*Ee];
__device__ float g_vec[(size_t)Bb*Nn*3*Ee];

// ---------------- generic NT SGEMM: C[r,j] = sum_k A[r,k] * W[j,k] ----------------
// mode 0: A = x (layout [N,B,E], logical row r=b*N+n), C = g_q (scaled)
// mode 1..3: same A, C = g_k/g_v/g_ve with extended-row layout (b*EXT + n)
// mode 4: A = g_xo (plain), C = Cout
// mode 5: A = g_vec (plain), C = Cout
__global__ void __launch_bounds__(256) gemm_all(const float* __restrict__ Ax,
                                                const float* __restrict__ W,
                                                float* __restrict__ Cout, int mode)
{
    __shared__ float As[16][128];
    __shared__ float Bs[16][64];
    const int t   = threadIdx.x;
    const int row0 = blockIdx.y * 128;
    const int col0 = blockIdx.x * 64;
    const int tx = t & 15, ty = t >> 4;

    float acc[8][4];
#pragma unroll
    for (int i = 0; i < 8; i++)
#pragma unroll
        for (int j = 0; j < 4; j++) acc[i][j] = 0.f;

    const int ra = row0 + (t >> 1);
    const float* arow;
    if (mode <= 3) {
        int b = ra >> 8, n = ra & 255;                // N = 256
        arow = Ax + ((size_t)n * Bb + b) * Ee;        // x[n, b, :]
    } else if (mode == 4) {
        arow = g_xo + (size_t)ra * Ee;
    } else {
        arow = g_vec + (size_t)ra * Ee;
    }
    arow += (t & 1) * 8;
    const float* brow = W + (size_t)(col0 + (t >> 2)) * Ee + (t & 3) * 4;

    const int ia = t >> 1, ka = (t & 1) * 8;
    const int jb = t >> 2, kb = (t & 3) * 4;

    for (int kk = 0; kk < Ee; kk += 16) {
        float4 a0 = *(const float4*)(arow + kk);
        float4 a1 = *(const float4*)(arow + kk + 4);
        float4 b0 = *(const float4*)(brow + kk);
        __syncthreads();
        As[ka+0][ia] = a0.x; As[ka+1][ia] = a0.y; As[ka+2][ia] = a0.z; As[ka+3][ia] = a0.w;
        As[ka+4][ia] = a1.x; As[ka+5][ia] = a1.y; As[ka+6][ia] = a1.z; As[ka+7][ia] = a1.w;
        Bs[kb+0][jb] = b0.x; Bs[kb+1][jb] = b0.y; Bs[kb+2][jb] = b0.z; Bs[kb+3][jb] = b0.w;
        __syncthreads();
#pragma unroll
        for (int k = 0; k < 16; k++) {
            float4 av0 = *(const float4*)&As[k][ty*8];
            float4 av1 = *(const float4*)&As[k][ty*8+4];
            float4 bv  = *(const float4*)&Bs[k][tx*4];
            float ar[8] = {av0.x,av0.y,av0.z,av0.w,av1.x,av1.y,av1.z,av1.w};
            float br[4] = {bv.x,bv.y,bv.z,bv.w};
#pragma unroll
            for (int i = 0; i < 8; i++)
#pragma unroll
                for (int j = 0; j < 4; j++)
                    acc[i][j] = fmaf(ar[i], br[j], acc[i][j]);
        }
    }

#pragma unroll
    for (int i = 0; i < 8; i++) {
        int r = row0 + ty*8 + i;
        int c = col0 + tx*4;
        float4 v = make_float4(acc[i][0], acc[i][1], acc[i][2], acc[i][3]);
        if (mode == 0) {
            v.x *= SCALING; v.y *= SCALING; v.z *= SCALING; v.w *= SCALING;
            *(float4*)&g_q[(size_t)r*Ee + c] = v;
        } else if (mode <= 3) {
            int b = r >> 8, n = r & 255;
            float* dst = (mode == 1) ? g_k : (mode == 2) ? g_v : g_ve;
            *(float4*)&dst[((size_t)b*EXTm + n)*Ee + c] = v;
        } else {
            *(float4*)&Cout[(size_t)r*Ee + c] = v;
        }
    }
}

// ---------------- gather: extend k/v/ve rows N..EXT via outcell_index ----------------
__global__ void __launch_bounds__(256) gather_kernel(const int* __restrict__ idx)
{
    int bm = blockIdx.x;
    int b = bm >> 9, m = bm & 511;                     // M = 512
    int s = idx[bm];
    size_t so = ((size_t)b*EXTm + s)      * Ee;
    size_t dd = ((size_t)b*EXTm + Nn + m) * Ee;
    int e = threadIdx.x * 4;                           // 256 threads * 4 = 1024 = E
    *(float4*)&g_k [dd+e] = *(const float4*)&g_k [so+e];
    *(float4*)&g_v [dd+e] = *(const float4*)&g_v [so+e];
    *(float4*)&g_ve[dd+e] = *(const float4*)&g_ve[so+e];
}

// ---------------- attention + softmax + equivariant outputs ----------------
struct AttnSmem {
    float4 pdt4[TN][64];       // p*delta per (ni, m-local); reused as reduction buffer
    float  Vt [64][32];
    float  VEt[64][32];
    float  s  [TN][769];       // scores -> probs
    float  sq [TN][32];
    float  posn[TN][4];
    unsigned int spm[TN];
};

__global__ void __launch_bounds__(512, 2) attn_kernel(
    const float* __restrict__ pos, const float* __restrict__ epos,
    const float* __restrict__ bias,
    const unsigned char* __restrict__ pmask, const unsigned char* __restrict__ emask)
{
    extern __shared__ char smraw[];
    AttnSmem& sm = *reinterpret_cast<AttnSmem*>(smraw);
    const int t  = threadIdx.x;
    const int nt = blockIdx.x & 15;            // N / TN = 16 tiles
    const int bh = blockIdx.x >> 4;
    const int h  = bh & 31, b = bh >> 5;
    const int n0 = nt * TN;

    // load q tile, query positions, query padding mask
    {
        int ni = t >> 5, d = t & 31;
        sm.sq[ni][d] = g_q[((size_t)(b*Nn + n0 + ni))*Ee + h*32 + d];
        if (d == 0) sm.spm[ni] = pmask[b*Nn + n0 + ni];
        if (d < 3)  sm.posn[ni][d] = pos[((size_t)b*Nn + n0 + ni)*3 + d];
    }
    __syncthreads();

    // -------- scores: each thread owns key rows m, dots against all TN queries --------
    for (int m = t; m < EXTm; m += 512) {
        unsigned int fm = (m < Nn) ? pmask[b*Nn + m] : emask[b*Mm + m - Nn];
        const float4* kr = (const float4*)(g_k + ((size_t)b*EXTm + m)*Ee + h*32);
        float4 kd[8];
#pragma unroll
        for (int i = 0; i < 8; i++) kd[i] = kr[i];
        const float* brow = bias + (((size_t)(b*Hh + h))*Nn + n0)*EXTm + m;
#pragma unroll
        for (int ni = 0; ni < TN; ni++) {
            const float4* q4 = (const float4*)sm.sq[ni];
            float acc = 0.f;
#pragma unroll
            for (int i = 0; i < 8; i++) {
                float4 qv = q4[i];
                acc = fmaf(qv.x, kd[i].x, acc);
                acc = fmaf(qv.y, kd[i].y, acc);
                acc = fmaf(qv.z, kd[i].z, acc);
                acc = fmaf(qv.w, kd[i].w, acc);
            }
            acc += brow[(size_t)ni * EXTm];
            if (fm | sm.spm[ni]) acc = NEGINF;
            sm.s[ni][m] = acc;
        }
    }
    __syncthreads();

    // -------- softmax: one warp per query row --------
    {
        int ni = t >> 5, lane = t & 31;
        float lm = NEGINF;
#pragma unroll
        for (int i = 0; i < 24; i++) lm = fmaxf(lm, sm.s[ni][lane + i*32]);
#pragma unroll
        for (int o = 16; o; o >>= 1) lm = fmaxf(lm, __shfl_xor_sync(0xffffffffu, lm, o));
        float ls = 0.f;
#pragma unroll
        for (int i = 0; i < 24; i++) {
            float p = __expf(sm.s[ni][lane + i*32] - lm);
            sm.s[ni][lane + i*32] = p;
            ls += p;
        }
#pragma unroll
        for (int o = 16; o; o >>= 1) ls += __shfl_xor_sync(0xffffffffu, ls, o);
        float inv = 1.f / ls;
#pragma unroll
        for (int i = 0; i < 24; i++) sm.s[ni][lane + i*32] *= inv;
    }

    // -------- output accumulation: threads = (g, ni, d-quad) --------
    const int dq  = t & 7;
    const int ni2 = (t >> 3) & 15;
    const int g   = t >> 7;                    // 4 m-interleave groups
    float4 a0 = make_float4(0,0,0,0), a1 = a0, a2 = a0, a3 = a0;

    for (int m0 = 0; m0 < EXTm; m0 += 64) {
        __syncthreads();                       // previous tile fully consumed
        {   // stage V / VE tiles (coalesced float4)
            int ml = t >> 3, d4 = (t & 7) * 4;
            *(float4*)&sm.Vt [ml][d4] = *(const float4*)(g_v  + ((size_t)b*EXTm + m0 + ml)*Ee + h*32 + d4);
            *(float4*)&sm.VEt[ml][d4] = *(const float4*)(g_ve + ((size_t)b*EXTm + m0 + ml)*Ee + h*32 + d4);
        }
        // p * delta for this m-tile
        for (int i = t; i < TN*64; i += 512) {
            int nii = i >> 6, ml = i & 63;
            int m = m0 + ml;
            float ax, ay, az; unsigned int fm;
            if (m < Nn) {
                const float* pp = pos + ((size_t)b*Nn + m)*3;
                ax = pp[0]; ay = pp[1]; az = pp[2];
                fm = pmask[b*Nn + m];
            } else {
                const float* pp = epos + ((size_t)b*Mm + (m - Nn))*3;
                ax = pp[0]; ay = pp[1]; az = pp[2];
                fm = emask[b*Mm + m - Nn];
            }
            float dx = sm.posn[nii][0] - ax;
            float dy = sm.posn[nii][1] - ay;
            float dz = sm.posn[nii][2] - az;
            float dist = sqrtf(dx*dx + dy*dy + dz*dz);
            if (sm.spm[nii] | fm) dist = 1e6f;
            float f = sm.s[nii][m] / (dist + 1.f);
            if (sm.spm[nii]) f = 0.f;
            sm.pdt4[nii][ml] = make_float4(dx*f, dy*f, dz*f, 0.f);
        }
        __syncthreads();
#pragma unroll
        for (int mi = 0; mi < 16; mi++) {
            int ml = g + mi*4;
            float4 vv  = *(const float4*)&sm.Vt [ml][dq*4];
            float4 vev = *(const float4*)&sm.VEt[ml][dq*4];
            float  p   = sm.s[ni2][m0 + ml];
            float4 pd  = sm.pdt4[ni2][ml];
            a0.x = fmaf(p, vev.x, a0.x); a0.y = fmaf(p, vev.y, a0.y);
            a0.z = fmaf(p, vev.z, a0.z); a0.w = fmaf(p, vev.w, a0.w);
            a1.x = fmaf(pd.x, vv.x, a1.x); a1.y = fmaf(pd.x, vv.y, a1.y);
            a1.z = fmaf(pd.x, vv.z, a1.z); a1.w = fmaf(pd.x, vv.w, a1.w);
            a2.x = fmaf(pd.y, vv.x, a2.x); a2.y = fmaf(pd.y, vv.y, a2.y);
            a2.z = fmaf(pd.y, vv.z, a2.z); a2.w = fmaf(pd.y, vv.w, a2.w);
            a3.x = fmaf(pd.z, vv.x, a3.x); a3.y = fmaf(pd.z, vv.y, a3.y);
            a3.z = fmaf(pd.z, vv.z, a3.z); a3.w = fmaf(pd.z, vv.w, a3.w);
        }
    }

    // -------- cross-group reduction (4 groups) and stores --------
    __syncthreads();
    float4* red = (float4*)&sm.pdt4[0][0];     // 1024-slot float4 scratch
    const size_t rowb = (size_t)(b*Nn + n0 + ni2);
    const int    coff = h*32 + dq*4;

    red[t] = a0; __syncthreads();
    if (g == 0) {
        float4 r0 = red[t], r1 = red[t+128], r2 = red[t+256], r3 = red[t+384];
        r0.x += r1.x + r2.x + r3.x; r0.y += r1.y + r2.y + r3.y;
        r0.z += r1.z + r2.z + r3.z; r0.w += r1.w + r2.w + r3.w;
        *(float4*)&g_xo[rowb*Ee + coff] = r0;
    }
    __syncthreads();
    red[t] = a1; __syncthreads();
    if (g == 0) {
        float4 r0 = red[t], r1 = red[t+128], r2 = red[t+256], r3 = red[t+384];
        r0.x += r1.x + r2.x + r3.x; r0.y += r1.y + r2.y + r3.y;
        r0.z += r1.z + r2.z + r3.z; r0.w += r1.w + r2.w + r3.w;
        *(float4*)&g_vec[(rowb*3 + 0)*Ee + coff] = r0;
    }
    __syncthreads();
    red[t] = a2; __syncthreads();
    if (g == 0) {
        float4 r0 = red[t], r1 = red[t+128], r2 = red[t+256], r3 = red[t+384];
        r0.x += r1.x + r2.x + r3.x; r0.y += r1.y + r2.y + r3.y;
        r0.z += r1.z + r2.z + r3.z; r0.w += r1.w + r2.w + r3.w;
        *(float4*)&g_vec[(rowb*3 + 1)*Ee + coff] = r0;
    }
    __syncthreads();
    red[t] = a3; __syncthreads();
    if (g == 0) {
        float4 r0 = red[t], r1 = red[t+128], r2 = red[t+256], r3 = red[t+384];
        r0.x += r1.x + r2.x + r3.x; r0.y += r1.y + r2.y + r3.y;
        r0.z += r1.z + r2.z + r3.z; r0.w += r1.w + r2.w + r3.w;
        *(float4*)&g_vec[(rowb*3 + 2)*Ee + coff] = r0;
    }
}

// ---------------- host entry ----------------
extern "C" void kernel_launch(void* const* d_in, const int* in_sizes, int n_in,
                              void* d_out, int out_size)
{
    const float* x    = (const float*)d_in[0];
    const float* pos  = (const float*)d_in[1];
    const float* epos = (const float*)d_in[2];
    const float* bias = (const float*)d_in[3];
    const unsigned char* pmask = (const unsigned char*)d_in[4];
    const unsigned char* emask = (const unsigned char*)d_in[5];
    const int*   idx  = (const int*)d_in[6];
    const float* Wq   = (const float*)d_in[7];
    const float* Wk   = (const float*)d_in[8];
    const float* Wv   = (const float*)d_in[9];
    const float* Wve  = (const float*)d_in[10];
    const float* Wo   = (const float*)d_in[11];
    const float* Woe  = (const float*)d_in[12];
    float* out = (float*)d_out;

    cudaFuncSetAttribute(attn_kernel, cudaFuncAttributeMaxDynamicSharedMemorySize,
                         (int)sizeof(AttnSmem));

    dim3 g16(16, 16, 1);
    gemm_all<<<g16, 256>>>(x, Wq,  nullptr, 0);
    gemm_all<<<g16, 256>>>(x, Wk,  nullptr, 1);
    gemm_all<<<g16, 256>>>(x, Wv,  nullptr, 2);
    gemm_all<<<g16, 256>>>(x, Wve, nullptr, 3);

    gather_kernel<<<Bb*Mm, 256>>>(idx);

    attn_kernel<<<Bb*Hh*(Nn/TN), 512, sizeof(AttnSmem)>>>(pos, epos, bias, pmask, emask);

    gemm_all<<<g16, 256>>>(nullptr, Woe, out, 4);                              // xo @ Woe^T
    gemm_all<<<dim3(16, 48, 1), 256>>>(nullptr, Wo, out + (size_t)Bb*Nn*Ee, 5); // vec @ Wo^T
}